// round 4
// baseline (speedup 1.0000x reference)
#include <cuda_runtime.h>
#include <cuda_bf16.h>
#include <cstdint>

// ---------------------------------------------------------------------------
// StackRNN fused kernel, v4: batch-pair packed into f32x2 (FFMA2).
// 8 warps: 2 state + 1 mem + 4 buf + 1 update. One barrier/step.
// All recurrent tensors stored batch-interleaved: element (k) holds the
// pair (g0,g1) in 8 bytes. One fma.rn.f32x2 processes both batches.
// ---------------------------------------------------------------------------

#define NOUT 210
#define B_TOT 256
#define SEQ 1024
#define NTHREADS 256

typedef unsigned long long ull;

__device__ __forceinline__ ull ffma2(ull a, ull b, ull c) {
    ull d; asm("fma.rn.f32x2 %0,%1,%2,%3;" : "=l"(d) : "l"(a), "l"(b), "l"(c)); return d;
}
__device__ __forceinline__ ull fmul2(ull a, ull b) {
    ull d; asm("mul.rn.f32x2 %0,%1,%2;" : "=l"(d) : "l"(a), "l"(b)); return d;
}
__device__ __forceinline__ ull fadd2(ull a, ull b) {
    ull d; asm("add.rn.f32x2 %0,%1,%2;" : "=l"(d) : "l"(a), "l"(b)); return d;
}
__device__ __forceinline__ ull fsub2(ull a, ull b) {
    return fadd2(a, b ^ 0x8000000080000000ULL);
}
__device__ __forceinline__ ull pack2(float lo, float hi) {
    ull d; asm("mov.b64 %0,{%1,%2};" : "=l"(d) : "f"(lo), "f"(hi)); return d;
}
__device__ __forceinline__ float lo2(ull v) { return __uint_as_float((unsigned)v); }
__device__ __forceinline__ float hi2(ull v) { return __uint_as_float((unsigned)(v >> 32)); }
__device__ __forceinline__ ull rcp2(ull v) {
    return pack2(__fdividef(1.f, lo2(v)), __fdividef(1.f, hi2(v)));
}

__device__ __align__(16) float g_E[128 * NOUT];
__device__ __align__(16) float g_CW[80 * NOUT];
__device__ __align__(16) float g_c[NOUT];

__global__ void precompute_kernel(
    const float* __restrict__ embed,
    const float* __restrict__ w_state, const float* __restrict__ b_state,
    const float* __restrict__ w_top,   const float* __restrict__ b_top,
    const float* __restrict__ w_mem,   const float* __restrict__ b_mem,
    const float* __restrict__ w_buf,   const float* __restrict__ b_buf,
    const float* __restrict__ w_st,    const float* __restrict__ b_st)
{
    __shared__ float wcol[768];
    int n = blockIdx.x;
    const float* W; const float* bias; int N, col;
    if (n < 64)       { W = w_st;  bias = b_st;  N = 64;  col = n; }
    else if (n < 82)  { W = w_mem; bias = b_mem; N = 18;  col = n - 64; }
    else              { W = w_buf; bias = b_buf; N = 128; col = n - 82; }

    int tid = threadIdx.x;
    for (int i = tid; i < 768; i += 256) wcol[i] = W[i * N + col];
    __syncthreads();

    if (tid < 128) {
        const float* er = embed + tid * 256;
        float s = 0.f;
        for (int h = 0; h < 256; h++) s += er[h] * wcol[h];
        g_E[tid * NOUT + n] = s;
    } else if (tid < 192) {
        int r = tid - 128;
        const float* wr = w_state + r * 256;
        float s = 0.f;
        for (int h = 0; h < 256; h++) s += wr[h] * wcol[256 + h];
        g_CW[r * NOUT + n] = s;
    } else if (tid < 208) {
        int r = tid - 192;
        const float* wr = w_top + r * 256;
        float s = 0.f;
        for (int h = 0; h < 256; h++) s += wr[h] * wcol[512 + h];
        g_CW[(64 + r) * NOUT + n] = s;
    } else if (tid == 208) {
        float s = bias[col];
        for (int h = 0; h < 256; h++) s += b_state[h] * wcol[256 + h];
        for (int h = 0; h < 256; h++) s += b_top[h]   * wcol[512 + h];
        g_c[n] = s;
    }
}

// Shared floats (all recurrent arrays batch-interleaved, pair = (g0,g1)):
//   sE     @ 0     : 26880                [tok][n] scalar
//   sTok   @ 26880 : 2048 ints            [g][t]
//   sStack @ 28928 : [ping][d][v][g] 2*64*16*2 = 4096
//   sSt    @ 33024 : [ping][k][g]   2*64*2 = 256   raw state exps
//   sZs    @ 33280 : [ping][j][g]   2*8*2  = 32    partial Z sums
//   sTop   @ 33312 : [ping][v][g]   2*16*2 = 64    raw top~ (scale Zm)
//   sZm    @ 33376 : [ping][g]      4 (+4 pad)
//   sPr    @ 33384 : [ping][j][g]   2*20*2 = 80    j:0=e_pop,1=e_noop,2=Z,4..19=e_push
#define SMEM_FLOATS 33464

// lagged full stack update, packed over both batches. pr = sPr+ping*40.
__device__ __forceinline__ void stack_update(const float* pr, const float* Pb,
                                             float* Qb, int lane)
{
    ull pe0 = *(const ull*)(pr + 0);
    ull pe1 = *(const ull*)(pr + 2);
    ull Zr  = *(const ull*)(pr + 4);
    ull iz = rcp2(Zr);
    ull ppop  = fmul2(pe0, iz);
    ull pnoop = fmul2(pe1, iz);
    ull ppush = fmul2(fsub2(fsub2(Zr, pe0), pe1), iz);
    const int c = lane & 3;
    const int d0 = (lane >> 2) * 8;
    ulonglong2 pva = *(const ulonglong2*)(pr + (4 + 4 * c) * 2);
    ulonglong2 pvb = *(const ulonglong2*)(pr + (4 + 4 * c) * 2 + 4);
    ull pv0 = fmul2(pva.x, iz), pv1 = fmul2(pva.y, iz);
    ull pv2 = fmul2(pvb.x, iz), pv3 = fmul2(pvb.y, iz);

    ull prev0 = 0, prev1 = 0, prev2 = 0, prev3 = 0;
    if (d0 != 0) {
        ulonglong2 a = *(const ulonglong2*)(Pb + (d0 - 1) * 32 + c * 8);
        ulonglong2 b = *(const ulonglong2*)(Pb + (d0 - 1) * 32 + c * 8 + 4);
        prev0 = a.x; prev1 = a.y; prev2 = b.x; prev3 = b.y;
    }
    ulonglong2 ca = *(const ulonglong2*)(Pb + d0 * 32 + c * 8);
    ulonglong2 cb = *(const ulonglong2*)(Pb + d0 * 32 + c * 8 + 4);
    ull cur0 = ca.x, cur1 = ca.y, cur2 = cb.x, cur3 = cb.y;

#pragma unroll
    for (int i = 0; i < 8; i++) {
        int d = d0 + i;
        ull n0, n1, n2, n3;
        if (d == 63) {
            n0 = (c == 0) ? pack2(1.f, 1.f) : 0ULL;
            n1 = 0; n2 = 0; n3 = 0;
        } else {
            ulonglong2 na = *(const ulonglong2*)(Pb + (d + 1) * 32 + c * 8);
            ulonglong2 nb = *(const ulonglong2*)(Pb + (d + 1) * 32 + c * 8 + 4);
            n0 = na.x; n1 = na.y; n2 = nb.x; n3 = nb.y;
        }
        ull o0 = fmul2(pnoop, cur0); o0 = ffma2(ppush, prev0, o0); o0 = ffma2(ppop, n0, o0);
        ull o1 = fmul2(pnoop, cur1); o1 = ffma2(ppush, prev1, o1); o1 = ffma2(ppop, n1, o1);
        ull o2 = fmul2(pnoop, cur2); o2 = ffma2(ppush, prev2, o2); o2 = ffma2(ppop, n2, o2);
        ull o3 = fmul2(pnoop, cur3); o3 = ffma2(ppush, prev3, o3); o3 = ffma2(ppop, n3, o3);
        if (d == 0) {
            o0 = fadd2(o0, pv0); o1 = fadd2(o1, pv1);
            o2 = fadd2(o2, pv2); o3 = fadd2(o3, pv3);
        }
        *(ulonglong2*)(Qb + d * 32 + c * 8)     = make_ulonglong2(o0, o1);
        *(ulonglong2*)(Qb + d * 32 + c * 8 + 4) = make_ulonglong2(o2, o3);
        prev0 = cur0; prev1 = cur1; prev2 = cur2; prev3 = cur3;
        cur0 = n0; cur1 = n1; cur2 = n2; cur3 = n3;
    }
}

__global__ __launch_bounds__(NTHREADS, 1)
void stackrnn_kernel(const int* __restrict__ x, float* __restrict__ out)
{
    extern __shared__ float sm[];
    float* sE     = sm;
    int*   sTok   = (int*)(sm + 26880);
    float* sStack = sm + 28928;
    float* sSt    = sm + 33024;
    float* sZs    = sm + 33280;
    float* sTop   = sm + 33312;
    float* sZm    = sm + 33376;
    float* sPr    = sm + 33384;

    const int tid  = threadIdx.x;
    const int wid  = tid >> 5;
    const int lane = tid & 31;
    const int b0   = blockIdx.x * 2;

    // ---- one-time setup ----
    {
        const float4* src = (const float4*)g_E;
        float4* dst = (float4*)sE;
        for (int i = tid; i < (128 * NOUT) / 4; i += NTHREADS) dst[i] = src[i];
    }
    for (int i = tid; i < 2 * SEQ; i += NTHREADS) {
        int g = i >> 10, r = i & 1023;
        sTok[i] = x[(size_t)(b0 + g) * SEQ + r];
    }
    // stack ping0: pair (1,1) at v==0 -> float index (i & 30) == 0
    for (int i = tid; i < 2048; i += NTHREADS) sStack[i] = ((i & 30) == 0) ? 1.f : 0.f;
    if (tid < 128) sSt[tid] = 0.f;
    if (tid < 16)  sZs[tid] = 0.125f;
    if (tid < 32)  sTop[tid] = (tid < 2) ? 1.f : 0.f;
    if (tid < 2)   sZm[tid] = 1.f;
    if (tid < 40)  sPr[tid] = (tid == 2 || tid == 3 || tid == 4 || tid == 5) ? 1.f : 0.f;
    // (j=1 noop pair at floats 2,3 ; j=2 Z pair at floats 4,5)

    // ---- roles ----
    const bool isState  = (wid < 2);
    const bool isMem    = (wid == 2);
    const bool isUpdate = (wid == 7);
    int mycol;
    if (isState)       mycol = wid * 32 + lane;
    else if (isMem)    mycol = 64 + (lane < 18 ? lane : 0);
    else if (isUpdate) mycol = 0;
    else               mycol = 82 + (wid - 3) * 32 + lane;

    ull W[80];
    float cn = 0.f;
    if (!isUpdate) {
        cn = g_c[mycol];
#pragma unroll
        for (int k = 0; k < 80; k++) {
            unsigned u = __float_as_uint(g_CW[k * NOUT + mycol]);
            W[k] = ((ull)u << 32) | u;
        }
    }
    __syncthreads();

    // mem-warp carried head state (lanes 0-15 hold component v=lane), packed pairs
    ull h0r = (lane == 0) ? pack2(1.f, 1.f) : 0ULL;   // raw, scale Zp
    ull h1r = (lane == 0) ? pack2(1.f, 1.f) : 0ULL;
    ull e0p = 0ULL, e1p = pack2(1.f, 1.f), Zp = pack2(1.f, 1.f);

    int ping = 0;
    const size_t outB0 = (size_t)b0 * (SEQ * 128);
    const size_t outB1 = (size_t)(b0 + 1) * (SEQ * 128);

    // prefetch token/E base for t=0
    ull baseNext = 0ULL;
    if (!isUpdate) {
        int tk0 = sTok[0], tk1 = sTok[SEQ];
        baseNext = pack2(cn + sE[tk0 * NOUT + mycol], cn + sE[tk1 * NOUT + mycol]);
    }

    for (int t = 0; t < SEQ; t++) {
        if (isUpdate) {
            stack_update(sPr + ping * 40, sStack + ping * 2048,
                         sStack + (ping ^ 1) * 2048, lane);
        } else {
            // ---- mem-warp pre-dot: normalize head, reconstruct row 2 ----
            ull h0 = 0, h1 = 0, h2 = 0;
            if (isMem) {
                ull izp = rcp2(Zp);
                h0 = fmul2(h0r, izp);  h1 = fmul2(h1r, izp);
                ull s1 = 0, s2 = 0, s3 = 0;
                if (lane < 16) {
                    const float* SB = sStack + ping * 2048;
                    s1 = *(const ull*)(SB + 32 + lane * 2);
                    s2 = *(const ull*)(SB + 64 + lane * 2);
                    s3 = *(const ull*)(SB + 96 + lane * 2);
                }
                ull ppm = fmul2(fsub2(fsub2(Zp, e0p), e1p), izp);
                h2 = fadd2(fadd2(fmul2(ppm, s1), fmul2(fmul2(e0p, izp), s3)),
                           fmul2(fmul2(e1p, izp), s2));
            }

            // ---- packed dot ----
            ull zp;
            {
                const ulonglong2* Z8 = (const ulonglong2*)(sZs + ping * 16);
                ulonglong2 za = Z8[0], zb = Z8[1], zc = Z8[2], zd = Z8[3];
                zp = fadd2(fadd2(fadd2(za.x, za.y), fadd2(zb.x, zb.y)),
                           fadd2(fadd2(zc.x, zc.y), fadd2(zd.x, zd.y)));
            }
            const ull invZs = rcp2(zp);
            const ull invZm = rcp2(*(const ull*)(sZm + ping * 2));
            const ull base = baseNext;

            const ulonglong2* S = (const ulonglong2*)(sSt + ping * 128);
            ull a0 = 0, a1 = 0, a2 = 0, a3 = 0, a4 = 0, a5 = 0, a6 = 0, a7 = 0;
#pragma unroll
            for (int k8 = 0; k8 < 8; k8++) {
                ulonglong2 pA = S[4 * k8], pB = S[4 * k8 + 1];
                ulonglong2 pC = S[4 * k8 + 2], pD = S[4 * k8 + 3];
                a0 = ffma2(W[8 * k8 + 0], pA.x, a0);
                a1 = ffma2(W[8 * k8 + 1], pA.y, a1);
                a2 = ffma2(W[8 * k8 + 2], pB.x, a2);
                a3 = ffma2(W[8 * k8 + 3], pB.y, a3);
                a4 = ffma2(W[8 * k8 + 4], pC.x, a4);
                a5 = ffma2(W[8 * k8 + 5], pC.y, a5);
                a6 = ffma2(W[8 * k8 + 6], pD.x, a6);
                a7 = ffma2(W[8 * k8 + 7], pD.y, a7);
            }
            const ulonglong2* T = (const ulonglong2*)(sTop + ping * 32);
            ull u0 = 0, u1 = 0, u2 = 0, u3 = 0;
#pragma unroll
            for (int k8 = 0; k8 < 2; k8++) {
                ulonglong2 pA = T[4 * k8], pB = T[4 * k8 + 1];
                ulonglong2 pC = T[4 * k8 + 2], pD = T[4 * k8 + 3];
                u0 = ffma2(W[64 + 8 * k8 + 0], pA.x, u0);
                u1 = ffma2(W[64 + 8 * k8 + 1], pA.y, u1);
                u2 = ffma2(W[64 + 8 * k8 + 2], pB.x, u2);
                u3 = ffma2(W[64 + 8 * k8 + 3], pB.y, u3);
                u0 = ffma2(W[64 + 8 * k8 + 4], pC.x, u0);
                u1 = ffma2(W[64 + 8 * k8 + 5], pC.y, u1);
                u2 = ffma2(W[64 + 8 * k8 + 6], pD.x, u2);
                u3 = ffma2(W[64 + 8 * k8 + 7], pD.y, u3);
            }
            ull dS = fadd2(fadd2(fadd2(a0, a1), fadd2(a2, a3)),
                           fadd2(fadd2(a4, a5), fadd2(a6, a7)));
            ull dT = fadd2(fadd2(u0, u1), fadd2(u2, u3));
            ull r = fadd2(base, fadd2(fmul2(invZs, dS), fmul2(invZm, dT)));
            float r0 = lo2(r), r1 = hi2(r);

            // prefetch next step's token/E base (read-only table, race-free)
            if (t + 1 < SEQ) {
                int tk0 = sTok[t + 1], tk1 = sTok[SEQ + t + 1];
                baseNext = pack2(cn + sE[tk0 * NOUT + mycol],
                                 cn + sE[tk1 * NOUT + mycol]);
            }

            if (isState) {
                ull e = pack2(__expf(r0), __expf(r1));
                *(ull*)(sSt + (ping ^ 1) * 128 + mycol * 2) = e;
                ull ps = e;
                ps = fadd2(ps, __shfl_xor_sync(0xffffffffu, ps, 1));
                ps = fadd2(ps, __shfl_xor_sync(0xffffffffu, ps, 2));
                ps = fadd2(ps, __shfl_xor_sync(0xffffffffu, ps, 4));
                if ((lane & 7) == 0)
                    *(ull*)(sZs + (ping ^ 1) * 16 + (wid * 4 + (lane >> 3)) * 2) = ps;
            } else if (isMem) {
                ull e = (lane < 18) ? pack2(__expf(r0), __expf(r1)) : 0ULL;
                ull E0 = __shfl_sync(0xffffffffu, e, 0);
                ull E1 = __shfl_sync(0xffffffffu, e, 1);
                ull ep = __shfl_sync(0xffffffffu, e, (2 + lane) & 31);
                ull Zt = e;
                Zt = fadd2(Zt, __shfl_xor_sync(0xffffffffu, Zt, 16));
                Zt = fadd2(Zt, __shfl_xor_sync(0xffffffffu, Zt, 8));
                Zt = fadd2(Zt, __shfl_xor_sync(0xffffffffu, Zt, 4));
                Zt = fadd2(Zt, __shfl_xor_sync(0xffffffffu, Zt, 2));
                Zt = fadd2(Zt, __shfl_xor_sync(0xffffffffu, Zt, 1));

                ull topn = fadd2(fadd2(fmul2(E1, h0), fmul2(E0, h1)), ep);
                ull h1n  = fadd2(fadd2(fmul2(fsub2(fsub2(Zt, E0), E1), h0),
                                       fmul2(E0, h2)), fmul2(E1, h1));

                if (lane < 16) *(ull*)(sTop + (ping ^ 1) * 32 + lane * 2) = topn;
                int pidx = (lane < 2) ? lane : lane + 2;
                if (lane < 18) *(ull*)(sPr + (ping ^ 1) * 40 + pidx * 2) = e;
                if (lane == 0) {
                    *(ull*)(sPr + (ping ^ 1) * 40 + 4) = Zt;
                    *(ull*)(sZm + (ping ^ 1) * 2) = Zt;
                }
                h0r = topn; h1r = h1n; e0p = E0; e1p = E1; Zp = Zt;
            } else {
                int v = mycol - 82;
                out[outB0 + (size_t)t * 128 + v] = r0;
                out[outB1 + (size_t)t * 128 + v] = r1;
            }
        }
        __syncthreads();
        ping ^= 1;
    }

    // ---- epilogue: apply probs_{S-1} -> stack_S ----
    if (isUpdate) {
        stack_update(sPr + ping * 40, sStack + ping * 2048,
                     sStack + (ping ^ 1) * 2048, lane);
    }
    __syncthreads();

    // ---- finals ----
    const size_t fsOff = (size_t)B_TOT * SEQ * 128;
    const size_t stOff = fsOff + (size_t)B_TOT * 64 * 16;
    for (int i = tid; i < 2048; i += NTHREADS) {
        int g = i & 1, v = (i >> 1) & 15, d = i >> 5;
        out[fsOff + (size_t)(b0 + g) * 1024 + d * 16 + v] =
            sStack[(ping ^ 1) * 2048 + i];
    }
    if (tid < 128) {
        int k = tid >> 1, g = tid & 1;
        float zsum = 0.f;
        for (int j = 0; j < 8; j++) zsum += sZs[ping * 16 + j * 2 + g];
        out[stOff + (size_t)(b0 + g) * 64 + k] =
            sSt[ping * 128 + k * 2 + g] * __fdividef(1.f, zsum);
    }
}

extern "C" void kernel_launch(void* const* d_in, const int* in_sizes, int n_in,
                              void* d_out, int out_size)
{
    const int*   x       = (const int*)  d_in[0];
    const float* embed   = (const float*)d_in[1];
    const float* w_state = (const float*)d_in[2];
    const float* b_state = (const float*)d_in[3];
    const float* w_top   = (const float*)d_in[4];
    const float* b_top   = (const float*)d_in[5];
    const float* w_mem   = (const float*)d_in[6];
    const float* b_mem   = (const float*)d_in[7];
    const float* w_buf   = (const float*)d_in[8];
    const float* b_buf   = (const float*)d_in[9];
    const float* w_st    = (const float*)d_in[10];
    const float* b_st    = (const float*)d_in[11];
    float* out = (float*)d_out;

    precompute_kernel<<<NOUT, 256>>>(embed, w_state, b_state, w_top, b_top,
                                     w_mem, b_mem, w_buf, b_buf, w_st, b_st);

    cudaFuncSetAttribute(stackrnn_kernel,
                         cudaFuncAttributeMaxDynamicSharedMemorySize,
                         SMEM_FLOATS * sizeof(float));
    stackrnn_kernel<<<B_TOT / 2, NTHREADS, SMEM_FLOATS * sizeof(float)>>>(x, out);
}

// round 5
// speedup vs baseline: 1.0610x; 1.0610x over previous
#include <cuda_runtime.h>
#include <cuda_bf16.h>
#include <cstdint>

// ---------------------------------------------------------------------------
// StackRNN fused kernel, v5: v3's 16-warp structure + K-packed f32x2 dots +
// deferred mem-warp softmax tail. One barrier per step.
//
// Columns (N=210): [0,64) state logits, [64,82) mem-action, [82,210) buffer.
// Weights K-packed: W[k] = (CW[2k][col], CW[2k+1][col]) -> one FFMA2 = 2 K.
// Softmaxes stored unnormalized (raw exps) + depth-2 partial sums; consumers
// fold 1/Z into their dots. Mem warp finishes its own Z next step (3 shfl,
// overlapped with dot loads) and defers the h1 head-row update likewise.
// ---------------------------------------------------------------------------

#define NOUT 210
#define B_TOT 256
#define SEQ 1024
#define NTHREADS 512

typedef unsigned long long ull;

__device__ __forceinline__ ull ffma2(ull a, ull b, ull c) {
    ull d; asm("fma.rn.f32x2 %0,%1,%2,%3;" : "=l"(d) : "l"(a), "l"(b), "l"(c)); return d;
}
__device__ __forceinline__ ull fadd2(ull a, ull b) {
    ull d; asm("add.rn.f32x2 %0,%1,%2;" : "=l"(d) : "l"(a), "l"(b)); return d;
}
__device__ __forceinline__ ull pack2(float lo, float hi) {
    ull d; asm("mov.b64 %0,{%1,%2};" : "=l"(d) : "f"(lo), "f"(hi)); return d;
}
__device__ __forceinline__ float lo2(ull v) { return __uint_as_float((unsigned)v); }
__device__ __forceinline__ float hi2(ull v) { return __uint_as_float((unsigned)(v >> 32)); }

__device__ __align__(16) float g_E[128 * NOUT];
__device__ __align__(16) float g_CW[80 * NOUT];
__device__ __align__(16) float g_c[NOUT];

__global__ void precompute_kernel(
    const float* __restrict__ embed,
    const float* __restrict__ w_state, const float* __restrict__ b_state,
    const float* __restrict__ w_top,   const float* __restrict__ b_top,
    const float* __restrict__ w_mem,   const float* __restrict__ b_mem,
    const float* __restrict__ w_buf,   const float* __restrict__ b_buf,
    const float* __restrict__ w_st,    const float* __restrict__ b_st)
{
    __shared__ float wcol[768];
    int n = blockIdx.x;
    const float* W; const float* bias; int N, col;
    if (n < 64)       { W = w_st;  bias = b_st;  N = 64;  col = n; }
    else if (n < 82)  { W = w_mem; bias = b_mem; N = 18;  col = n - 64; }
    else              { W = w_buf; bias = b_buf; N = 128; col = n - 82; }

    int tid = threadIdx.x;
    for (int i = tid; i < 768; i += 256) wcol[i] = W[i * N + col];
    __syncthreads();

    if (tid < 128) {
        const float* er = embed + tid * 256;
        float s = 0.f;
        for (int h = 0; h < 256; h++) s += er[h] * wcol[h];
        g_E[tid * NOUT + n] = s;
    } else if (tid < 192) {
        int r = tid - 128;
        const float* wr = w_state + r * 256;
        float s = 0.f;
        for (int h = 0; h < 256; h++) s += wr[h] * wcol[256 + h];
        g_CW[r * NOUT + n] = s;
    } else if (tid < 208) {
        int r = tid - 192;
        const float* wr = w_top + r * 256;
        float s = 0.f;
        for (int h = 0; h < 256; h++) s += wr[h] * wcol[512 + h];
        g_CW[(64 + r) * NOUT + n] = s;
    } else if (tid == 208) {
        float s = bias[col];
        for (int h = 0; h < 256; h++) s += b_state[h] * wcol[256 + h];
        for (int h = 0; h < 256; h++) s += b_top[h]   * wcol[512 + h];
        g_c[n] = s;
    }
}

// Shared floats:
//   sE     @ 0     : 26880            [tok][n]
//   sTok   @ 26880 : 2048 ints        [g][t]
//   sStack @ 28928 : [ping][g][64][16] = 4096
//   sSt    @ 33024 : [ping][g][64] = 256    raw state exps
//   sZs    @ 33280 : [ping][g][16] = 64     depth-2 state partials
//   sTop   @ 33344 : [ping][g][16] = 64     raw top~ (scale Zm)
//   sZmP   @ 33408 : [ping][g][8]  = 32     depth-2 mem partials
//   sPr    @ 33440 : [ping][g][20] = 80     [0]=e_pop,[1]=e_noop,[4..19]=e_push
#define SMEM_FLOATS 33520

__device__ __forceinline__ void stack_update(const float* pr, const float* zmp,
                                             const float* P, float* Q, int lane)
{
    float pe0 = pr[0], pe1 = pr[1];
    float4 za = *(const float4*)zmp;
    float4 zb = *(const float4*)(zmp + 4);
    float Zr = ((za.x + za.y) + (za.z + za.w)) + ((zb.x + zb.y) + (zb.z + zb.w));
    float iz = __fdividef(1.f, Zr);
    float ppop  = pe0 * iz;
    float pnoop = pe1 * iz;
    float ppush = (Zr - pe0 - pe1) * iz;
    const int c = lane & 3;
    const int d0 = (lane >> 2) * 8;
    float4 pv = ((const float4*)(pr + 4))[c];
    pv.x *= iz; pv.y *= iz; pv.z *= iz; pv.w *= iz;

    const float4* P4 = (const float4*)P;
    float4*       Q4 = (float4*)Q;
    float4 prev = (d0 == 0) ? make_float4(0.f, 0.f, 0.f, 0.f) : P4[(d0 - 1) * 4 + c];
    float4 cur  = P4[d0 * 4 + c];
#pragma unroll
    for (int i = 0; i < 8; i++) {
        int d = d0 + i;
        float4 nxt;
        if (d == 63) nxt = (c == 0) ? make_float4(1.f, 0.f, 0.f, 0.f)
                                    : make_float4(0.f, 0.f, 0.f, 0.f);
        else         nxt = P4[(d + 1) * 4 + c];
        float4 o;
        o.x = ppush * prev.x + ppop * nxt.x + pnoop * cur.x;
        o.y = ppush * prev.y + ppop * nxt.y + pnoop * cur.y;
        o.z = ppush * prev.z + ppop * nxt.z + pnoop * cur.z;
        o.w = ppush * prev.w + ppop * nxt.w + pnoop * cur.w;
        if (d == 0) { o.x += pv.x; o.y += pv.y; o.z += pv.z; o.w += pv.w; }
        Q4[d * 4 + c] = o;
        prev = cur; cur = nxt;
    }
}

__global__ __launch_bounds__(NTHREADS, 1)
void stackrnn_kernel(const int* __restrict__ x, float* __restrict__ out)
{
    extern __shared__ float sm[];
    float* sE     = sm;
    int*   sTok   = (int*)(sm + 26880);
    float* sStack = sm + 28928;
    float* sSt    = sm + 33024;
    float* sZs    = sm + 33280;
    float* sTop   = sm + 33344;
    float* sZmP   = sm + 33408;
    float* sPr    = sm + 33440;

    const int tid  = threadIdx.x;
    const int wid  = tid >> 5;
    const int lane = tid & 31;
    const int b0   = blockIdx.x * 2;

    // ---- one-time setup ----
    {
        const float4* src = (const float4*)g_E;
        float4* dst = (float4*)sE;
        for (int i = tid; i < (128 * NOUT) / 4; i += NTHREADS) dst[i] = src[i];
    }
    for (int i = tid; i < 2 * SEQ; i += NTHREADS) {
        int g = i >> 10, r = i & 1023;
        sTok[i] = x[(size_t)(b0 + g) * SEQ + r];
    }
    for (int i = tid; i < 2048; i += NTHREADS) sStack[i] = ((i & 15) == 0) ? 1.f : 0.f;
    if (tid < 128) sSt[tid] = 0.f;
    if (tid < 32)  sZs[tid]  = 0.0625f;                       // sums to 1
    if (tid < 32)  sTop[tid] = (tid == 0 || tid == 16) ? 1.f : 0.f;
    if (tid < 16)  sZmP[tid] = (tid == 0 || tid == 8) ? 1.f : 0.f;
    if (tid < 40)  sPr[tid]  = (tid == 1 || tid == 21) ? 1.f : 0.f;  // noop=1

    // ---- roles ----
    const bool isState  = (wid < 4);
    const bool isMem    = (wid == 4 || wid == 5);
    const bool isUpdate = (wid >= 14);
    int g, mycol;
    if (isState)       { g = wid >> 1;  mycol = (wid & 1) * 32 + lane; }
    else if (isMem)    { g = wid - 4;   mycol = 64 + (lane < 18 ? lane : 0); }
    else if (isUpdate) { g = wid - 14;  mycol = 0; }
    else               { int idx = tid - 192; g = idx >> 7; mycol = 82 + (idx & 127); }

    ull W[40];
    float cn = 0.f;
    if (!isUpdate) {
        cn = g_c[mycol];
#pragma unroll
        for (int k = 0; k < 40; k++)
            W[k] = pack2(g_CW[(2 * k) * NOUT + mycol], g_CW[(2 * k + 1) * NOUT + mycol]);
    }
    __syncthreads();

    // mem-warp carried regs (lanes 0..15 hold vocab component v=lane)
    float h0 = 0.f, h1 = 0.f, h2 = 0.f;      // normalized rows of current stack
    float topc = 0.f;                         // raw row0 of next stack (scale Zp)
    float cE0 = 0.f, cE1 = 1.f, cZp = 0.125f; // probs_{-1}=noop; Z partial
    if (isMem && lane == 0) { h0 = h1 = h2 = 1.f; topc = 1.f; }

    int ping = 0;
    const size_t outB = (size_t)(b0 + g) * (SEQ * 128);

    // prefetch E base for t=0
    float baseNext = 0.f;
    if (!isUpdate) baseNext = cn + sE[sTok[g * SEQ] * NOUT + mycol];

    for (int t = 0; t < SEQ; t++) {
        if (isUpdate) {
            stack_update(sPr + ping * 40 + g * 20, sZmP + ping * 16 + g * 8,
                         sStack + ping * 2048 + g * 1024,
                         sStack + (ping ^ 1) * 2048 + g * 1024, lane);
        } else {
            // ---- mem pre-dot: finish deferred Z, head rows (overlaps dot loads)
            if (isMem) {
                float Zp = cZp;
                Zp += __shfl_xor_sync(0xffffffffu, Zp, 4);
                Zp += __shfl_xor_sync(0xffffffffu, Zp, 8);
                Zp += __shfl_xor_sync(0xffffffffu, Zp, 16);
                float izp = __fdividef(1.f, Zp);
                float nh0 = topc * izp;
                float nh1 = ((Zp - cE0 - cE1) * h0 + cE0 * h2 + cE1 * h1) * izp;
                float s1 = 0.f, s2 = 0.f, s3 = 0.f;
                const float* SB = sStack + ping * 2048 + g * 1024;
                if (lane < 16) { s1 = SB[16 + lane]; s2 = SB[32 + lane]; s3 = SB[48 + lane]; }
                float nh2 = ((Zp - cE0 - cE1) * s1 + cE0 * s3 + cE1 * s2) * izp;
                h0 = nh0; h1 = nh1; h2 = nh2;
            }

            // ---- normalizers from partials ----
            const ulonglong2* ZS = (const ulonglong2*)(sZs + ping * 32 + g * 16);
            ulonglong2 z0 = ZS[0], z1 = ZS[1], z2 = ZS[2], z3 = ZS[3];
            ull zz = fadd2(fadd2(fadd2(z0.x, z0.y), fadd2(z1.x, z1.y)),
                           fadd2(fadd2(z2.x, z2.y), fadd2(z3.x, z3.y)));
            const float invZs = __fdividef(1.f, lo2(zz) + hi2(zz));
            const ulonglong2* ZM = (const ulonglong2*)(sZmP + ping * 16 + g * 8);
            ulonglong2 m0 = ZM[0], m1 = ZM[1];
            ull mm = fadd2(fadd2(m0.x, m0.y), fadd2(m1.x, m1.y));
            const float invZm = __fdividef(1.f, lo2(mm) + hi2(mm));
            const float base = baseNext;

            // ---- K-packed dot ----
            const ulonglong2* S = (const ulonglong2*)(sSt + ping * 128 + g * 64);
            ull a0 = 0, a1 = 0, a2 = 0, a3 = 0;
#pragma unroll
            for (int i = 0; i < 8; i++) {
                ulonglong2 p = S[2 * i], q = S[2 * i + 1];
                a0 = ffma2(W[4 * i + 0], p.x, a0);
                a1 = ffma2(W[4 * i + 1], p.y, a1);
                a2 = ffma2(W[4 * i + 2], q.x, a2);
                a3 = ffma2(W[4 * i + 3], q.y, a3);
            }
            const ulonglong2* T = (const ulonglong2*)(sTop + ping * 32 + g * 16);
            ulonglong2 t0 = T[0], t1 = T[1], t2 = T[2], t3 = T[3];
            ull u0 = 0, u1 = 0, u2 = 0, u3 = 0;
            u0 = ffma2(W[32], t0.x, u0);  u1 = ffma2(W[33], t0.y, u1);
            u2 = ffma2(W[34], t1.x, u2);  u3 = ffma2(W[35], t1.y, u3);
            u0 = ffma2(W[36], t2.x, u0);  u1 = ffma2(W[37], t2.y, u1);
            u2 = ffma2(W[38], t3.x, u2);  u3 = ffma2(W[39], t3.y, u3);

            ull A = fadd2(fadd2(a0, a1), fadd2(a2, a3));
            ull U = fadd2(fadd2(u0, u1), fadd2(u2, u3));
            const float r = base + invZs * (lo2(A) + hi2(A)) + invZm * (lo2(U) + hi2(U));

            // prefetch next step's E base (read-only tables, race-free)
            if (t + 1 < SEQ)
                baseNext = cn + sE[sTok[g * SEQ + t + 1] * NOUT + mycol];

            if (isState) {
                float e = __expf(r);
                sSt[(ping ^ 1) * 128 + g * 64 + mycol] = e;
                float ps = e;
                ps += __shfl_xor_sync(0xffffffffu, ps, 1);
                ps += __shfl_xor_sync(0xffffffffu, ps, 2);
                if ((lane & 3) == 0)
                    sZs[(ping ^ 1) * 32 + g * 16 + (wid & 1) * 8 + (lane >> 2)] = ps;
            } else if (isMem) {
                float e = (lane < 18) ? __expf(r) : 0.f;
                float E0 = __shfl_sync(0xffffffffu, e, 0);
                float E1 = __shfl_sync(0xffffffffu, e, 1);
                float ep = __shfl_sync(0xffffffffu, e, 2 + (lane & 15));
                float topn = E1 * h0 + E0 * h1 + ep;          // raw, scale Zt
                if (lane < 16) sTop[(ping ^ 1) * 32 + g * 16 + lane] = topn;
                int pidx = (lane < 2) ? lane : lane + 2;
                if (lane < 18) sPr[(ping ^ 1) * 40 + g * 20 + pidx] = e;
                float pz = e;
                pz += __shfl_xor_sync(0xffffffffu, pz, 1);
                pz += __shfl_xor_sync(0xffffffffu, pz, 2);
                if ((lane & 3) == 0) sZmP[(ping ^ 1) * 16 + g * 8 + (lane >> 2)] = pz;
                topc = topn; cE0 = E0; cE1 = E1; cZp = pz;     // finish next step
            } else {
                out[outB + (size_t)t * 128 + (mycol - 82)] = r;
            }
        }
        __syncthreads();
        ping ^= 1;
    }

    // ---- epilogue: apply probs_{S-1} -> stack_S ----
    if (isUpdate) {
        stack_update(sPr + ping * 40 + g * 20, sZmP + ping * 16 + g * 8,
                     sStack + ping * 2048 + g * 1024,
                     sStack + (ping ^ 1) * 2048 + g * 1024, lane);
    }
    __syncthreads();

    // ---- finals ----
    const size_t fsOff = (size_t)B_TOT * SEQ * 128;
    const size_t stOff = fsOff + (size_t)B_TOT * 64 * 16;
    for (int i = tid; i < 2048; i += NTHREADS) {
        int gg = i >> 10, r = i & 1023;
        out[fsOff + (size_t)(b0 + gg) * 1024 + r] = sStack[(ping ^ 1) * 2048 + i];
    }
    if (tid < 128) {
        int gg = tid >> 6;
        float zs = 0.f;
        for (int j = 0; j < 16; j++) zs += sZs[ping * 32 + gg * 16 + j];
        out[stOff + (size_t)(b0 + gg) * 64 + (tid & 63)] =
            sSt[ping * 128 + tid] * __fdividef(1.f, zs);
    }
}

extern "C" void kernel_launch(void* const* d_in, const int* in_sizes, int n_in,
                              void* d_out, int out_size)
{
    const int*   x       = (const int*)  d_in[0];
    const float* embed   = (const float*)d_in[1];
    const float* w_state = (const float*)d_in[2];
    const float* b_state = (const float*)d_in[3];
    const float* w_top   = (const float*)d_in[4];
    const float* b_top   = (const float*)d_in[5];
    const float* w_mem   = (const float*)d_in[6];
    const float* b_mem   = (const float*)d_in[7];
    const float* w_buf   = (const float*)d_in[8];
    const float* b_buf   = (const float*)d_in[9];
    const float* w_st    = (const float*)d_in[10];
    const float* b_st    = (const float*)d_in[11];
    float* out = (float*)d_out;

    precompute_kernel<<<NOUT, 256>>>(embed, w_state, b_state, w_top, b_top,
                                     w_mem, b_mem, w_buf, b_buf, w_st, b_st);

    cudaFuncSetAttribute(stackrnn_kernel,
                         cudaFuncAttributeMaxDynamicSharedMemorySize,
                         SMEM_FLOATS * sizeof(float));
    stackrnn_kernel<<<B_TOT / 2, NTHREADS, SMEM_FLOATS * sizeof(float)>>>(x, out);
}

// round 6
// speedup vs baseline: 1.1751x; 1.1075x over previous
#include <cuda_runtime.h>
#include <cuda_bf16.h>
#include <cstdint>

// ---------------------------------------------------------------------------
// StackRNN fused kernel, v6: producer/consumer split with named barriers.
//
// Group A (warps 0-7, 256 thr): 4 state + 2 mem + 2 update warps. One
//   bar.sync(1,256) per step. Writes per-step slots into a DEPTH-4 ring.
// Group B (warps 8-15, 256 thr): buffer-logit warps, lag <=3 steps behind,
//   consuming ring slots. Per slot s: ready barrier id 2+s (A arrives, B
//   syncs), free barrier id 6+s (B arrives, A syncs before rewriting).
//
// Columns (N=210): [0,64) state logits, [64,82) mem-action, [82,210) buffer.
// Weights K-packed for f32x2 FFMA2. Softmaxes kept unnormalized with
// partial-sum Z folding (as v5). Stack update runs one step lagged.
// ---------------------------------------------------------------------------

#define NOUT 210
#define B_TOT 256
#define SEQ 1024
#define NTHREADS 512

#define BAR_SYNC(id, cnt)   asm volatile("bar.sync %0, %1;"   :: "r"(id), "r"(cnt) : "memory")
#define BAR_ARRIVE(id, cnt) asm volatile("bar.arrive %0, %1;" :: "r"(id), "r"(cnt) : "memory")

typedef unsigned long long ull;

__device__ __forceinline__ ull ffma2(ull a, ull b, ull c) {
    ull d; asm("fma.rn.f32x2 %0,%1,%2,%3;" : "=l"(d) : "l"(a), "l"(b), "l"(c)); return d;
}
__device__ __forceinline__ ull fadd2(ull a, ull b) {
    ull d; asm("add.rn.f32x2 %0,%1,%2;" : "=l"(d) : "l"(a), "l"(b)); return d;
}
__device__ __forceinline__ ull pack2(float lo, float hi) {
    ull d; asm("mov.b64 %0,{%1,%2};" : "=l"(d) : "f"(lo), "f"(hi)); return d;
}
__device__ __forceinline__ float lo2(ull v) { return __uint_as_float((unsigned)v); }
__device__ __forceinline__ float hi2(ull v) { return __uint_as_float((unsigned)(v >> 32)); }

__device__ __align__(16) float g_E[128 * NOUT];
__device__ __align__(16) float g_CW[80 * NOUT];
__device__ __align__(16) float g_c[NOUT];

__global__ void precompute_kernel(
    const float* __restrict__ embed,
    const float* __restrict__ w_state, const float* __restrict__ b_state,
    const float* __restrict__ w_top,   const float* __restrict__ b_top,
    const float* __restrict__ w_mem,   const float* __restrict__ b_mem,
    const float* __restrict__ w_buf,   const float* __restrict__ b_buf,
    const float* __restrict__ w_st,    const float* __restrict__ b_st)
{
    __shared__ float wcol[768];
    int n = blockIdx.x;
    const float* W; const float* bias; int N, col;
    if (n < 64)       { W = w_st;  bias = b_st;  N = 64;  col = n; }
    else if (n < 82)  { W = w_mem; bias = b_mem; N = 18;  col = n - 64; }
    else              { W = w_buf; bias = b_buf; N = 128; col = n - 82; }

    int tid = threadIdx.x;
    for (int i = tid; i < 768; i += 256) wcol[i] = W[i * N + col];
    __syncthreads();

    if (tid < 128) {
        const float* er = embed + tid * 256;
        float s = 0.f;
        for (int h = 0; h < 256; h++) s += er[h] * wcol[h];
        g_E[tid * NOUT + n] = s;
    } else if (tid < 192) {
        int r = tid - 128;
        const float* wr = w_state + r * 256;
        float s = 0.f;
        for (int h = 0; h < 256; h++) s += wr[h] * wcol[256 + h];
        g_CW[r * NOUT + n] = s;
    } else if (tid < 208) {
        int r = tid - 192;
        const float* wr = w_top + r * 256;
        float s = 0.f;
        for (int h = 0; h < 256; h++) s += wr[h] * wcol[512 + h];
        g_CW[(64 + r) * NOUT + n] = s;
    } else if (tid == 208) {
        float s = bias[col];
        for (int h = 0; h < 256; h++) s += b_state[h] * wcol[256 + h];
        for (int h = 0; h < 256; h++) s += b_top[h]   * wcol[512 + h];
        g_c[n] = s;
    }
}

// Shared floats:
//   sE     @ 0     : 26880            [tok][n]
//   sTok   @ 26880 : 2048 ints        [g][t]
//   sStack @ 28928 : [ping][g][64][16] = 4096   (depth 2, A-only)
//   sSt    @ 33024 : [slot][g][64] = 512        raw state exps (depth 4)
//   sZs    @ 33536 : [slot][g][16] = 128        state Z partials (depth 4)
//   sTop   @ 33664 : [slot][g][16] = 128        raw top~ (depth 4)
//   sZmP   @ 33792 : [slot][g][8]  = 64         mem Z partials (depth 4)
//   sPr    @ 33856 : [ping][g][20] = 80         raw probs (depth 2, A-only)
#define SMEM_FLOATS 33936

__device__ __forceinline__ void stack_update(const float* pr, const float* zmp,
                                             const float* P, float* Q, int lane)
{
    float pe0 = pr[0], pe1 = pr[1];
    float4 za = *(const float4*)zmp;
    float4 zb = *(const float4*)(zmp + 4);
    float Zr = ((za.x + za.y) + (za.z + za.w)) + ((zb.x + zb.y) + (zb.z + zb.w));
    float iz = __fdividef(1.f, Zr);
    float ppop  = pe0 * iz;
    float pnoop = pe1 * iz;
    float ppush = (Zr - pe0 - pe1) * iz;
    const int c = lane & 3;
    const int d0 = (lane >> 2) * 8;
    float4 pv = ((const float4*)(pr + 4))[c];
    pv.x *= iz; pv.y *= iz; pv.z *= iz; pv.w *= iz;

    const float4* P4 = (const float4*)P;
    float4*       Q4 = (float4*)Q;
    float4 prev = (d0 == 0) ? make_float4(0.f, 0.f, 0.f, 0.f) : P4[(d0 - 1) * 4 + c];
    float4 cur  = P4[d0 * 4 + c];
#pragma unroll
    for (int i = 0; i < 8; i++) {
        int d = d0 + i;
        float4 nxt;
        if (d == 63) nxt = (c == 0) ? make_float4(1.f, 0.f, 0.f, 0.f)
                                    : make_float4(0.f, 0.f, 0.f, 0.f);
        else         nxt = P4[(d + 1) * 4 + c];
        float4 o;
        o.x = ppush * prev.x + ppop * nxt.x + pnoop * cur.x;
        o.y = ppush * prev.y + ppop * nxt.y + pnoop * cur.y;
        o.z = ppush * prev.z + ppop * nxt.z + pnoop * cur.z;
        o.w = ppush * prev.w + ppop * nxt.w + pnoop * cur.w;
        if (d == 0) { o.x += pv.x; o.y += pv.y; o.z += pv.z; o.w += pv.w; }
        Q4[d * 4 + c] = o;
        prev = cur; cur = nxt;
    }
}

__global__ __launch_bounds__(NTHREADS, 1)
void stackrnn_kernel(const int* __restrict__ x, float* __restrict__ out)
{
    extern __shared__ float sm[];
    float* sE     = sm;
    int*   sTok   = (int*)(sm + 26880);
    float* sStack = sm + 28928;
    float* sSt    = sm + 33024;
    float* sZs    = sm + 33536;
    float* sTop   = sm + 33664;
    float* sZmP   = sm + 33792;
    float* sPr    = sm + 33856;

    const int tid  = threadIdx.x;
    const int wid  = tid >> 5;
    const int lane = tid & 31;
    const int b0   = blockIdx.x * 2;

    // ---- one-time setup ----
    {
        const float4* src = (const float4*)g_E;
        float4* dst = (float4*)sE;
        for (int i = tid; i < (128 * NOUT) / 4; i += NTHREADS) dst[i] = src[i];
    }
    for (int i = tid; i < 2 * SEQ; i += NTHREADS) {
        int g = i >> 10, r = i & 1023;
        sTok[i] = x[(size_t)(b0 + g) * SEQ + r];
    }
    for (int i = tid; i < 2048; i += NTHREADS) sStack[i] = ((i & 15) == 0) ? 1.f : 0.f;
    if (tid < 128) sSt[tid] = 0.f;                            // slot 0
    if (tid < 32)  sZs[tid]  = 0.0625f;                       // slot 0: sums to 1
    if (tid < 32)  sTop[tid] = (tid == 0 || tid == 16) ? 1.f : 0.f;
    if (tid < 16)  sZmP[tid] = (tid == 0 || tid == 8) ? 1.f : 0.f;
    if (tid < 40)  sPr[tid]  = (tid == 1 || tid == 21) ? 1.f : 0.f;  // noop=1

    // ---- roles ----
    const bool isState  = (wid < 4);
    const bool isMem    = (wid == 4 || wid == 5);
    const bool isUpdate = (wid == 6 || wid == 7);
    const bool isBuf    = (wid >= 8);
    int g, mycol;
    if (isState)       { g = wid >> 1;  mycol = (wid & 1) * 32 + lane; }
    else if (isMem)    { g = wid - 4;   mycol = 64 + (lane < 18 ? lane : 0); }
    else if (isUpdate) { g = wid - 6;   mycol = 0; }
    else               { int idx = tid - 256; g = idx >> 7; mycol = 82 + (idx & 127); }

    ull W[40];
    float cn = 0.f;
    if (!isUpdate) {
        cn = g_c[mycol];
#pragma unroll
        for (int k = 0; k < 40; k++)
            W[k] = pack2(g_CW[(2 * k) * NOUT + mycol], g_CW[(2 * k + 1) * NOUT + mycol]);
    }
    __syncthreads();

    if (isBuf) {
        // =================== GROUP B: buffer logits, lagged ===================
        const size_t outB = (size_t)(b0 + g) * (SEQ * 128);
        float baseNext = cn + sE[sTok[g * SEQ] * NOUT + mycol];
        for (int t = 0; t < SEQ; t++) {
            const int sCur = t & 3;
            BAR_SYNC(2 + sCur, 512);          // wait slot ready

            const ulonglong2* ZS = (const ulonglong2*)(sZs + sCur * 32 + g * 16);
            ulonglong2 z0 = ZS[0], z1 = ZS[1], z2 = ZS[2], z3 = ZS[3];
            ull zz = fadd2(fadd2(fadd2(z0.x, z0.y), fadd2(z1.x, z1.y)),
                           fadd2(fadd2(z2.x, z2.y), fadd2(z3.x, z3.y)));
            const float invZs = __fdividef(1.f, lo2(zz) + hi2(zz));
            const ulonglong2* ZM = (const ulonglong2*)(sZmP + sCur * 16 + g * 8);
            ulonglong2 m0 = ZM[0], m1 = ZM[1];
            ull mm = fadd2(fadd2(m0.x, m0.y), fadd2(m1.x, m1.y));
            const float invZm = __fdividef(1.f, lo2(mm) + hi2(mm));
            const float base = baseNext;

            const ulonglong2* S = (const ulonglong2*)(sSt + sCur * 128 + g * 64);
            ull a0 = 0, a1 = 0, a2 = 0, a3 = 0;
#pragma unroll
            for (int i = 0; i < 8; i++) {
                ulonglong2 p = S[2 * i], q = S[2 * i + 1];
                a0 = ffma2(W[4 * i + 0], p.x, a0);
                a1 = ffma2(W[4 * i + 1], p.y, a1);
                a2 = ffma2(W[4 * i + 2], q.x, a2);
                a3 = ffma2(W[4 * i + 3], q.y, a3);
            }
            const ulonglong2* T = (const ulonglong2*)(sTop + sCur * 32 + g * 16);
            ulonglong2 t0 = T[0], t1 = T[1], t2 = T[2], t3 = T[3];
            ull u0 = ffma2(W[32], t0.x, 0ULL), u1 = ffma2(W[33], t0.y, 0ULL);
            ull u2 = ffma2(W[34], t1.x, 0ULL), u3 = ffma2(W[35], t1.y, 0ULL);
            u0 = ffma2(W[36], t2.x, u0);  u1 = ffma2(W[37], t2.y, u1);
            u2 = ffma2(W[38], t3.x, u2);  u3 = ffma2(W[39], t3.y, u3);

            ull A = fadd2(fadd2(a0, a1), fadd2(a2, a3));
            ull U = fadd2(fadd2(u0, u1), fadd2(u2, u3));
            const float r = base + invZs * (lo2(A) + hi2(A)) + invZm * (lo2(U) + hi2(U));
            out[outB + (size_t)t * 128 + (mycol - 82)] = r;

            if (t + 1 < SEQ)
                baseNext = cn + sE[sTok[g * SEQ + t + 1] * NOUT + mycol];
            BAR_ARRIVE(6 + sCur, 512);        // release slot
        }
    } else {
        // =================== GROUP A: recurrence ===================
        // mem-warp carried regs (lanes 0..15 hold vocab component v=lane)
        float h0 = 0.f, h1 = 0.f, h2 = 0.f;      // normalized rows of current stack
        float topc = 0.f;                         // raw row0 of next stack
        float cE0 = 0.f, cE1 = 1.f, cZp = 0.125f; // probs_{-1}=noop; Z partial
        if (isMem && lane == 0) { h0 = h1 = h2 = 1.f; topc = 1.f; }

        float baseNext = 0.f;
        if (!isUpdate) baseNext = cn + sE[sTok[g * SEQ] * NOUT + mycol];

        BAR_ARRIVE(2 + 0, 512);                   // slot 0 (initial state) ready

        for (int t = 0; t < SEQ; t++) {
            const int sCur  = t & 3;
            const int sNext = (t + 1) & 3;
            const int ping  = t & 1;
            if (t >= 3) BAR_SYNC(6 + sNext, 512); // wait B freed the slot we rewrite

            if (isUpdate) {
                stack_update(sPr + ping * 40 + g * 20, sZmP + sCur * 16 + g * 8,
                             sStack + ping * 2048 + g * 1024,
                             sStack + (ping ^ 1) * 2048 + g * 1024, lane);
            } else {
                // mem pre-dot: finish deferred Z + head rows (overlaps dot loads)
                if (isMem) {
                    float Zp = cZp;
                    Zp += __shfl_xor_sync(0xffffffffu, Zp, 4);
                    Zp += __shfl_xor_sync(0xffffffffu, Zp, 8);
                    Zp += __shfl_xor_sync(0xffffffffu, Zp, 16);
                    float izp = __fdividef(1.f, Zp);
                    float nh0 = topc * izp;
                    float nh1 = ((Zp - cE0 - cE1) * h0 + cE0 * h2 + cE1 * h1) * izp;
                    float s1 = 0.f, s2 = 0.f, s3 = 0.f;
                    const float* SB = sStack + ping * 2048 + g * 1024;
                    if (lane < 16) { s1 = SB[16 + lane]; s2 = SB[32 + lane]; s3 = SB[48 + lane]; }
                    float nh2 = ((Zp - cE0 - cE1) * s1 + cE0 * s3 + cE1 * s2) * izp;
                    h0 = nh0; h1 = nh1; h2 = nh2;
                }

                const ulonglong2* ZS = (const ulonglong2*)(sZs + sCur * 32 + g * 16);
                ulonglong2 z0 = ZS[0], z1 = ZS[1], z2 = ZS[2], z3 = ZS[3];
                ull zz = fadd2(fadd2(fadd2(z0.x, z0.y), fadd2(z1.x, z1.y)),
                               fadd2(fadd2(z2.x, z2.y), fadd2(z3.x, z3.y)));
                const float invZs = __fdividef(1.f, lo2(zz) + hi2(zz));
                const ulonglong2* ZM = (const ulonglong2*)(sZmP + sCur * 16 + g * 8);
                ulonglong2 m0 = ZM[0], m1 = ZM[1];
                ull mm = fadd2(fadd2(m0.x, m0.y), fadd2(m1.x, m1.y));
                const float invZm = __fdividef(1.f, lo2(mm) + hi2(mm));
                const float base = baseNext;

                const ulonglong2* S = (const ulonglong2*)(sSt + sCur * 128 + g * 64);
                ull a0 = 0, a1 = 0, a2 = 0, a3 = 0;
#pragma unroll
                for (int i = 0; i < 8; i++) {
                    ulonglong2 p = S[2 * i], q = S[2 * i + 1];
                    a0 = ffma2(W[4 * i + 0], p.x, a0);
                    a1 = ffma2(W[4 * i + 1], p.y, a1);
                    a2 = ffma2(W[4 * i + 2], q.x, a2);
                    a3 = ffma2(W[4 * i + 3], q.y, a3);
                }
                const ulonglong2* T = (const ulonglong2*)(sTop + sCur * 32 + g * 16);
                ulonglong2 t0 = T[0], t1 = T[1], t2 = T[2], t3 = T[3];
                ull u0 = ffma2(W[32], t0.x, 0ULL), u1 = ffma2(W[33], t0.y, 0ULL);
                ull u2 = ffma2(W[34], t1.x, 0ULL), u3 = ffma2(W[35], t1.y, 0ULL);
                u0 = ffma2(W[36], t2.x, u0);  u1 = ffma2(W[37], t2.y, u1);
                u2 = ffma2(W[38], t3.x, u2);  u3 = ffma2(W[39], t3.y, u3);

                ull A = fadd2(fadd2(a0, a1), fadd2(a2, a3));
                ull U = fadd2(fadd2(u0, u1), fadd2(u2, u3));
                const float r = base + invZs * (lo2(A) + hi2(A)) + invZm * (lo2(U) + hi2(U));

                if (t + 1 < SEQ)
                    baseNext = cn + sE[sTok[g * SEQ + t + 1] * NOUT + mycol];

                if (isState) {
                    float e = __expf(r);
                    sSt[sNext * 128 + g * 64 + mycol] = e;
                    float ps = e;
                    ps += __shfl_xor_sync(0xffffffffu, ps, 1);
                    ps += __shfl_xor_sync(0xffffffffu, ps, 2);
                    if ((lane & 3) == 0)
                        sZs[sNext * 32 + g * 16 + (wid & 1) * 8 + (lane >> 2)] = ps;
                } else {  // mem
                    float e = (lane < 18) ? __expf(r) : 0.f;
                    float E0 = __shfl_sync(0xffffffffu, e, 0);
                    float E1 = __shfl_sync(0xffffffffu, e, 1);
                    float ep = __shfl_sync(0xffffffffu, e, 2 + (lane & 15));
                    float topn = E1 * h0 + E0 * h1 + ep;          // raw, scale Zt
                    if (lane < 16) sTop[sNext * 32 + g * 16 + lane] = topn;
                    int pidx = (lane < 2) ? lane : lane + 2;
                    if (lane < 18) sPr[(ping ^ 1) * 40 + g * 20 + pidx] = e;
                    float pz = e;
                    pz += __shfl_xor_sync(0xffffffffu, pz, 1);
                    pz += __shfl_xor_sync(0xffffffffu, pz, 2);
                    if ((lane & 3) == 0) sZmP[sNext * 16 + g * 8 + (lane >> 2)] = pz;
                    topc = topn; cE0 = E0; cE1 = E1; cZp = pz;
                }
            }
            BAR_ARRIVE(2 + sNext, 512);   // slot sNext ready for B (after own writes)
            BAR_SYNC(1, 256);             // A-internal step barrier
        }

        // epilogue: apply probs_{S-1} -> stack_S  (probs in sPr[0], Z in slot 0)
        if (isUpdate) {
            stack_update(sPr + 0 * 40 + g * 20, sZmP + 0 * 16 + g * 8,
                         sStack + 0 * 2048 + g * 1024,
                         sStack + 1 * 2048 + g * 1024, lane);
        }
    }
    __syncthreads();

    // ---- finals ----
    const size_t fsOff = (size_t)B_TOT * SEQ * 128;
    const size_t stOff = fsOff + (size_t)B_TOT * 64 * 16;
    for (int i = tid; i < 2048; i += NTHREADS) {
        int gg = i >> 10, r = i & 1023;
        out[fsOff + (size_t)(b0 + gg) * 1024 + r] = sStack[2048 + i];
    }
    if (tid < 128) {
        int gg = tid >> 6;
        float zs = 0.f;
        for (int j = 0; j < 16; j++) zs += sZs[gg * 16 + j];   // slot 0
        out[stOff + (size_t)(b0 + gg) * 64 + (tid & 63)] =
            sSt[tid] * __fdividef(1.f, zs);                    // slot 0
    }
}

extern "C" void kernel_launch(void* const* d_in, const int* in_sizes, int n_in,
                              void* d_out, int out_size)
{
    const int*   x       = (const int*)  d_in[0];
    const float* embed   = (const float*)d_in[1];
    const float* w_state = (const float*)d_in[2];
    const float* b_state = (const float*)d_in[3];
    const float* w_top   = (const float*)d_in[4];
    const float* b_top   = (const float*)d_in[5];
    const float* w_mem   = (const float*)d_in[6];
    const float* b_mem   = (const float*)d_in[7];
    const float* w_buf   = (const float*)d_in[8];
    const float* b_buf   = (const float*)d_in[9];
    const float* w_st    = (const float*)d_in[10];
    const float* b_st    = (const float*)d_in[11];
    float* out = (float*)d_out;

    precompute_kernel<<<NOUT, 256>>>(embed, w_state, b_state, w_top, b_top,
                                     w_mem, b_mem, w_buf, b_buf, w_st, b_st);

    cudaFuncSetAttribute(stackrnn_kernel,
                         cudaFuncAttributeMaxDynamicSharedMemorySize,
                         SMEM_FLOATS * sizeof(float));
    stackrnn_kernel<<<B_TOT / 2, NTHREADS, SMEM_FLOATS * sizeof(float)>>>(x, out);
}